// round 12
// baseline (speedup 1.0000x reference)
#include <cuda_runtime.h>
#include <cuda_fp16.h>
#include <cstdint>
#include <cstddef>

// Problem dims (fixed by the dataset)
#define BB 8
#define TC 2048
#define TQ 1024
#define DD 1024

// ---------------- scratch (allocation-free: __device__ globals) ----------------
__device__ __align__(256) __half g_attn[(size_t)BB * TC * TQ];  // fp16 softmax probs, 32 MiB
__device__ __align__(256) __half g_qt[(size_t)BB * DD * TQ];    // fp16 qencode^T [b][d][q], 16 MiB
__device__ int g_flagA[BB * 16];                                // per (b, ctile) softmax-done flags

// ---------------- helpers ----------------
__device__ __forceinline__ uint32_t smem_u32(const void* p) {
    uint32_t a;
    asm("{ .reg .u64 t; cvta.to.shared.u64 t, %1; cvt.u32.u64 %0, t; }" : "=r"(a) : "l"(p));
    return a;
}
__device__ __forceinline__ void cp_async16(uint32_t s, const void* g) {
    asm volatile("cp.async.cg.shared.global [%0], [%1], 16;" :: "r"(s), "l"(g) : "memory");
}
__device__ __forceinline__ void cp_commit() {
    asm volatile("cp.async.commit_group;" ::: "memory");
}
template <int N>
__device__ __forceinline__ void cp_wait() {
    asm volatile("cp.async.wait_group %0;" :: "n"(N) : "memory");
}
__device__ __forceinline__ void ldsm_x4(uint32_t& r0, uint32_t& r1, uint32_t& r2, uint32_t& r3,
                                        uint32_t addr) {
    asm volatile("ldmatrix.sync.aligned.m8n8.x4.shared.b16 {%0,%1,%2,%3}, [%4];"
                 : "=r"(r0), "=r"(r1), "=r"(r2), "=r"(r3) : "r"(addr));
}
// m16n8k16 fp16 MMA, fp32 accumulate
__device__ __forceinline__ void mma_f16(float& c0, float& c1, float& c2, float& c3,
                                        uint32_t a0, uint32_t a1, uint32_t a2, uint32_t a3,
                                        uint32_t b0, uint32_t b1) {
    asm volatile(
        "mma.sync.aligned.m16n8k16.row.col.f32.f16.f16.f32 "
        "{%0,%1,%2,%3}, {%4,%5,%6,%7}, {%8,%9}, {%0,%1,%2,%3};"
        : "+f"(c0), "+f"(c1), "+f"(c2), "+f"(c3)
        : "r"(a0), "r"(a1), "r"(a2), "r"(a3), "r"(b0), "r"(b1));
}

// ---------------- kernel 1: transpose+convert qencode [b,q,d] fp32 -> g_qt [b,d,q] fp16 ----------------
__global__ __launch_bounds__(256) void transpose_kernel(const float* __restrict__ q) {
    __shared__ float tile[32][33];
    int dt = blockIdx.x, qt = blockIdx.y, b = blockIdx.z;
    int tx = threadIdx.x & 31, ty = threadIdx.x >> 5;
    const float* src = q + (size_t)b * TQ * DD;
    #pragma unroll
    for (int i = 0; i < 4; i++) {
        int qq = qt * 32 + ty + i * 8;
        tile[ty + i * 8][tx] = src[(size_t)qq * DD + dt * 32 + tx];
    }
    __syncthreads();
    __half* dst = g_qt + (size_t)b * DD * TQ;
    #pragma unroll
    for (int i = 0; i < 4; i++) {
        int d2 = dt * 32 + ty + i * 8;
        dst[(size_t)d2 * TQ + qt * 32 + tx] = __float2half_rn(tile[tx][ty + i * 8]);
    }
}

// ---------------- kernel 2: fused softmax-producer + FP16 mma.sync GEMM ----------------
// dtile==0 CTA computes softmax of its 128 A-rows into g_attn, sets flag; siblings spin.
// GEMM: CTA 128x128, 8 warps (2x4), warp tile 64x32, KC=64, 3-stage cp.async, 2 CTAs/SM. (R8 config)
static constexpr int KC = 64;
static constexpr int NCH = TQ / KC;              // 16 k-chunks
static constexpr int SROW = 72;                  // smem row stride (halves): conflict-free for ldmatrix
static constexpr int A_HALVES = 128 * SROW;      // 9216
static constexpr int A_BYTES = A_HALVES * 2;     // 18432
static constexpr int STAGE_BYTES = 2 * A_BYTES;  // 36864
static constexpr int STAGES = 3;
static constexpr int SMEM_BYTES = STAGES * STAGE_BYTES;  // 110592 (x2 CTAs = 221184 <= 228KB)

__global__ __launch_bounds__(256, 2) void gemm_fused_kernel(const float* __restrict__ sim,
                                                            float* __restrict__ out) {
    extern __shared__ __half smem[];
    const int tid = threadIdx.x;
    const int wid = tid >> 5, lane = tid & 31;
    const int g = lane >> 2, t = lane & 3;          // mma groupID / threadID-in-group
    const int wm = (wid & 1) * 64;                  // warp m offset within CTA tile
    const int wn = (wid >> 1) * 32;                 // warp n offset within CTA tile
    const int dtile = blockIdx.x, ctile = blockIdx.y, b = blockIdx.z;

    // ---- producer/consumer handoff for this (b, ctile) A-panel ----
    if (dtile == 0) {
        // softmax of rows [ctile*128, +128) of batch b: warp w handles rows w, w+8, ...
        const size_t row0 = (size_t)b * TC + (size_t)ctile * 128;
        for (int r = wid; r < 128; r += 8) {
            const float4* in = reinterpret_cast<const float4*>(sim + (row0 + r) * TQ);
            float4 v[8];
            #pragma unroll
            for (int j = 0; j < 8; j++) v[j] = in[lane + 32 * j];

            float m = -1e30f;
            #pragma unroll
            for (int j = 0; j < 8; j++)
                m = fmaxf(m, fmaxf(fmaxf(v[j].x, v[j].y), fmaxf(v[j].z, v[j].w)));
            #pragma unroll
            for (int o = 16; o > 0; o >>= 1) m = fmaxf(m, __shfl_xor_sync(0xFFFFFFFFu, m, o));

            float sum = 0.f;
            #pragma unroll
            for (int j = 0; j < 8; j++) {
                v[j].x = __expf(v[j].x - m); v[j].y = __expf(v[j].y - m);
                v[j].z = __expf(v[j].z - m); v[j].w = __expf(v[j].w - m);
                sum += (v[j].x + v[j].y) + (v[j].z + v[j].w);
            }
            #pragma unroll
            for (int o = 16; o > 0; o >>= 1) sum += __shfl_xor_sync(0xFFFFFFFFu, sum, o);
            const float inv = 1.0f / sum;

            uint2* orow = reinterpret_cast<uint2*>(g_attn + (row0 + r) * TQ);
            #pragma unroll
            for (int j = 0; j < 8; j++) {
                __half2 h01 = __floats2half2_rn(v[j].x * inv, v[j].y * inv);
                __half2 h23 = __floats2half2_rn(v[j].z * inv, v[j].w * inv);
                uint2 pk;
                pk.x = *reinterpret_cast<uint32_t*>(&h01);
                pk.y = *reinterpret_cast<uint32_t*>(&h23);
                orow[lane + 32 * j] = pk;
            }
        }
        __threadfence();
        __syncthreads();
        if (tid == 0) atomicExch(&g_flagA[b * 16 + ctile], 1);
    } else {
        if (tid == 0) {
            while (atomicAdd(&g_flagA[b * 16 + ctile], 0) == 0) __nanosleep(64);
        }
        __syncthreads();
        __threadfence();
    }

    // ---- GEMM (identical to R8 best) ----
    const __half* Ag = g_attn + ((size_t)b * TC + (size_t)ctile * 128) * TQ;
    const __half* Bg = g_qt + ((size_t)b * DD + (size_t)dtile * 128) * TQ;

    const uint32_t smem_base = smem_u32(smem);

    const int f_row0 = tid >> 3;            // +32 per i
    const int f_ch = tid & 7;               // 16B chunk within row

    auto fetch = [&](int kc, int stg) {
        uint32_t sa = smem_base + (uint32_t)(stg * STAGE_BYTES);
        uint32_t sb = sa + (uint32_t)A_BYTES;
        #pragma unroll
        for (int i = 0; i < 4; i++) {
            int row = f_row0 + i * 32;
            uint32_t so = (uint32_t)(row * SROW + f_ch * 8) * 2u;
            const __half* ag = Ag + (size_t)row * TQ + kc * KC + f_ch * 8;
            const __half* bg = Bg + (size_t)row * TQ + kc * KC + f_ch * 8;
            cp_async16(sa + so, ag);
            cp_async16(sb + so, bg);
        }
    };

    const int a_row = wm + (lane & 15);             // + i*16
    const int a_col = (lane >> 4) * 8;              // + k0
    const int b_row = wn + (lane & 7) + (lane >> 4) * 8;  // + j2*16
    const int b_col = ((lane >> 3) & 1) * 8;        // + k0

    float acc[4][4][4];
    #pragma unroll
    for (int i = 0; i < 4; i++)
        #pragma unroll
        for (int j = 0; j < 4; j++)
            #pragma unroll
            for (int r = 0; r < 4; r++) acc[i][j][r] = 0.f;

    fetch(0, 0); cp_commit();
    fetch(1, 1); cp_commit();

    for (int kc = 0; kc < NCH; kc++) {
        cp_wait<STAGES - 2>();
        __syncthreads();

        if (kc + 2 < NCH) fetch(kc + 2, (kc + 2) % STAGES);
        cp_commit();

        const int stg = kc % STAGES;
        const uint32_t sA = smem_base + (uint32_t)(stg * STAGE_BYTES);
        const uint32_t sB = sA + (uint32_t)A_BYTES;

        #pragma unroll
        for (int ks = 0; ks < 4; ks++) {
            const int k0 = ks * 16;
            uint32_t af[4][4], bf[4][2];
            #pragma unroll
            for (int i = 0; i < 4; i++)
                ldsm_x4(af[i][0], af[i][1], af[i][2], af[i][3],
                        sA + (uint32_t)((a_row + i * 16) * SROW + k0 + a_col) * 2u);
            #pragma unroll
            for (int j2 = 0; j2 < 2; j2++)
                ldsm_x4(bf[j2 * 2][0], bf[j2 * 2][1], bf[j2 * 2 + 1][0], bf[j2 * 2 + 1][1],
                        sB + (uint32_t)((b_row + j2 * 16) * SROW + k0 + b_col) * 2u);
            #pragma unroll
            for (int i = 0; i < 4; i++)
                #pragma unroll
                for (int j = 0; j < 4; j++)
                    mma_f16(acc[i][j][0], acc[i][j][1], acc[i][j][2], acc[i][j][3],
                            af[i][0], af[i][1], af[i][2], af[i][3],
                            bf[j][0], bf[j][1]);
        }
    }
    cp_wait<0>();

    // epilogue: direct global stores (float2 per fragment pair)
    const size_t orow0 = (size_t)b * TC + ctile * 128 + wm + g;
    const int col0 = dtile * 128 + wn + t * 2;
    #pragma unroll
    for (int i = 0; i < 4; i++) {
        float* p0 = out + (orow0 + i * 16) * DD + col0;
        float* p1 = p0 + 8 * DD;
        #pragma unroll
        for (int j = 0; j < 4; j++) {
            *reinterpret_cast<float2*>(p0 + j * 8) = make_float2(acc[i][j][0], acc[i][j][1]);
            *reinterpret_cast<float2*>(p1 + j * 8) = make_float2(acc[i][j][2], acc[i][j][3]);
        }
    }
}

// ---------------- launcher ----------------
extern "C" void kernel_launch(void* const* d_in, const int* in_sizes, int n_in,
                              void* d_out, int out_size) {
    const float* sim  = (const float*)d_in[0];   // [8, 2048, 1024] fp32
    const float* qenc = (const float*)d_in[1];   // [8, 1024, 1024] fp32
    float* out = (float*)d_out;                  // [8, 2048, 1024] fp32

    cudaFuncSetAttribute(gemm_fused_kernel, cudaFuncAttributeMaxDynamicSharedMemorySize, SMEM_BYTES);

    transpose_kernel<<<dim3(DD / 32, TQ / 32, BB), 256>>>(qenc);
    gemm_fused_kernel<<<dim3(DD / 128, TC / 128, BB), 256, SMEM_BYTES>>>(sim, out);
}

// round 13
// speedup vs baseline: 1.1632x; 1.1632x over previous
#include <cuda_runtime.h>
#include <cuda_fp16.h>
#include <cstdint>
#include <cstddef>

// Problem dims (fixed by the dataset)
#define BB 8
#define TC 2048
#define TQ 1024
#define DD 1024

// ---------------- scratch (allocation-free: __device__ globals) ----------------
__device__ __align__(256) __half g_attn[(size_t)BB * TC * TQ];  // fp16 softmax probs, 32 MiB
__device__ __align__(256) __half g_qt[(size_t)BB * DD * TQ];    // fp16 qencode^T [b][d][q], 16 MiB

// ---------------- helpers ----------------
__device__ __forceinline__ uint32_t smem_u32(const void* p) {
    uint32_t a;
    asm("{ .reg .u64 t; cvta.to.shared.u64 t, %1; cvt.u32.u64 %0, t; }" : "=r"(a) : "l"(p));
    return a;
}
__device__ __forceinline__ void cp_async16(uint32_t s, const void* g) {
    asm volatile("cp.async.cg.shared.global [%0], [%1], 16;" :: "r"(s), "l"(g) : "memory");
}
__device__ __forceinline__ void cp_commit() {
    asm volatile("cp.async.commit_group;" ::: "memory");
}
template <int N>
__device__ __forceinline__ void cp_wait() {
    asm volatile("cp.async.wait_group %0;" :: "n"(N) : "memory");
}
__device__ __forceinline__ void ldsm_x4(uint32_t& r0, uint32_t& r1, uint32_t& r2, uint32_t& r3,
                                        uint32_t addr) {
    asm volatile("ldmatrix.sync.aligned.m8n8.x4.shared.b16 {%0,%1,%2,%3}, [%4];"
                 : "=r"(r0), "=r"(r1), "=r"(r2), "=r"(r3) : "r"(addr));
}
// m16n8k16 fp16 MMA, fp32 accumulate
__device__ __forceinline__ void mma_f16(float& c0, float& c1, float& c2, float& c3,
                                        uint32_t a0, uint32_t a1, uint32_t a2, uint32_t a3,
                                        uint32_t b0, uint32_t b1) {
    asm volatile(
        "mma.sync.aligned.m16n8k16.row.col.f32.f16.f16.f32 "
        "{%0,%1,%2,%3}, {%4,%5,%6,%7}, {%8,%9}, {%0,%1,%2,%3};"
        : "+f"(c0), "+f"(c1), "+f"(c2), "+f"(c3)
        : "r"(a0), "r"(a1), "r"(a2), "r"(a3), "r"(b0), "r"(b1));
}

// ---------------- kernel 1: merged preprocessing (R8, proven) ----------------
static constexpr int N_SOFTMAX_BLOCKS = BB * TC / 8;                    // 2048
static constexpr int N_TRANSPOSE_BLOCKS = (DD / 32) * (TQ / 32) * BB;   // 8192

__global__ __launch_bounds__(256) void pre_kernel(const float* __restrict__ sim,
                                                  const float* __restrict__ q) {
    const int bid = blockIdx.x;
    const int tid = threadIdx.x;

    if (bid < N_SOFTMAX_BLOCKS) {
        const int warp = tid >> 5;
        const int lane = tid & 31;
        const size_t row = (size_t)bid * 8 + warp;

        const float4* in = reinterpret_cast<const float4*>(sim + row * TQ);
        float4 v[8];
        #pragma unroll
        for (int j = 0; j < 8; j++) v[j] = in[lane + 32 * j];

        float m = -1e30f;
        #pragma unroll
        for (int j = 0; j < 8; j++)
            m = fmaxf(m, fmaxf(fmaxf(v[j].x, v[j].y), fmaxf(v[j].z, v[j].w)));
        #pragma unroll
        for (int o = 16; o > 0; o >>= 1) m = fmaxf(m, __shfl_xor_sync(0xFFFFFFFFu, m, o));

        float sum = 0.f;
        #pragma unroll
        for (int j = 0; j < 8; j++) {
            v[j].x = __expf(v[j].x - m); v[j].y = __expf(v[j].y - m);
            v[j].z = __expf(v[j].z - m); v[j].w = __expf(v[j].w - m);
            sum += (v[j].x + v[j].y) + (v[j].z + v[j].w);
        }
        #pragma unroll
        for (int o = 16; o > 0; o >>= 1) sum += __shfl_xor_sync(0xFFFFFFFFu, sum, o);
        const float inv = 1.0f / sum;

        uint2* orow = reinterpret_cast<uint2*>(g_attn + row * TQ);
        #pragma unroll
        for (int j = 0; j < 8; j++) {
            __half2 h01 = __floats2half2_rn(v[j].x * inv, v[j].y * inv);
            __half2 h23 = __floats2half2_rn(v[j].z * inv, v[j].w * inv);
            uint2 pk;
            pk.x = *reinterpret_cast<uint32_t*>(&h01);
            pk.y = *reinterpret_cast<uint32_t*>(&h23);
            orow[lane + 32 * j] = pk;
        }
    } else {
        __shared__ float tile[32][33];
        const int t = bid - N_SOFTMAX_BLOCKS;
        const int dt = t & 31;
        const int qt = (t >> 5) & 31;
        const int b = t >> 10;
        const int tx = tid & 31;
        const int ty = tid >> 5;
        const float* src = q + (size_t)b * TQ * DD;
        #pragma unroll
        for (int i = 0; i < 4; i++) {
            int qq = qt * 32 + ty + i * 8;
            tile[ty + i * 8][tx] = src[(size_t)qq * DD + dt * 32 + tx];
        }
        __syncthreads();
        __half* dst = g_qt + (size_t)b * DD * TQ;
        #pragma unroll
        for (int i = 0; i < 4; i++) {
            int d2 = dt * 32 + ty + i * 8;
            dst[(size_t)d2 * TQ + qt * 32 + tx] = __float2half_rn(tile[tx][ty + i * 8]);
        }
    }
}

// ---------------- kernel 2: persistent FP16 mma.sync GEMM ----------------
// R8 core (CTA 128x128, 8 warps 2x4, warp tile 64x32, KC=64, 3-stage cp.async, 2 CTAs/SM),
// made persistent: each CTA processes tiles cta, cta+NCTA, ... with a FLAT chunk pipeline
// across tiles (next tile's first chunks prefetched during current tile's epilogue).
static constexpr int KC = 64;
static constexpr int NCH = TQ / KC;              // 16 k-chunks per tile
static constexpr int SROW = 72;                  // smem row stride (halves): ldmatrix conflict-free
static constexpr int A_HALVES = 128 * SROW;      // 9216
static constexpr int A_BYTES = A_HALVES * 2;     // 18432
static constexpr int STAGE_BYTES = 2 * A_BYTES;  // 36864
static constexpr int STAGES = 3;
static constexpr int SMEM_BYTES = STAGES * STAGE_BYTES;  // 110592 (x2 CTAs = 221184)
static constexpr int TOTAL_TILES = (DD / 128) * (TC / 128) * BB;  // 1024
static constexpr int NCTA = 304;                 // 2 CTAs/SM x 152 SMs

__global__ __launch_bounds__(256, 2) void gemm_f16_kernel(float* __restrict__ out) {
    extern __shared__ __half smem[];
    const int tid = threadIdx.x;
    const int wid = tid >> 5, lane = tid & 31;
    const int qg = lane >> 2, t = lane & 3;         // mma groupID / threadID-in-group
    const int wm = (wid & 1) * 64;
    const int wn = (wid >> 1) * 32;
    const int cta = blockIdx.x;

    const int ntiles = (TOTAL_TILES - cta + NCTA - 1) / NCTA;
    const int total = ntiles * NCH;

    const uint32_t smem_base = smem_u32(smem);

    const int f_row0 = tid >> 3;            // +32 per i
    const int f_ch = tid & 7;               // 16B chunk within row

    // fetch flat-chunk gc into ring stage gc%3
    auto fetch = [&](int gc) {
        const int tl = cta + (gc >> 4) * NCTA;
        const int kc = gc & 15;
        const int dt = tl & 7, ct = (tl >> 3) & 15, bb = tl >> 7;
        const __half* Ag = g_attn + ((size_t)bb * TC + (size_t)ct * 128) * TQ + kc * KC + f_ch * 8;
        const __half* Bg = g_qt + ((size_t)bb * DD + (size_t)dt * 128) * TQ + kc * KC + f_ch * 8;
        const int stg = gc % 3;
        uint32_t sa = smem_base + (uint32_t)(stg * STAGE_BYTES);
        uint32_t sb = sa + (uint32_t)A_BYTES;
        #pragma unroll
        for (int i = 0; i < 4; i++) {
            int row = f_row0 + i * 32;
            uint32_t so = (uint32_t)(row * SROW + f_ch * 8) * 2u;
            cp_async16(sa + so, Ag + (size_t)row * TQ);
            cp_async16(sb + so, Bg + (size_t)row * TQ);
        }
    };

    // ldmatrix per-lane addressing (precomputed)
    const int a_row = wm + (lane & 15);                   // + i*16
    const int a_col = (lane >> 4) * 8;                    // + k0
    const int b_row = wn + (lane & 7) + (lane >> 4) * 8;  // + j2*16
    const int b_col = ((lane >> 3) & 1) * 8;              // + k0

    float acc[4][4][4];
    #pragma unroll
    for (int i = 0; i < 4; i++)
        #pragma unroll
        for (int j = 0; j < 4; j++)
            #pragma unroll
            for (int r = 0; r < 4; r++) acc[i][j][r] = 0.f;

    fetch(0); cp_commit();
    fetch(1); cp_commit();

    int tile = cta;
    for (int gc = 0; gc < total; gc++) {
        cp_wait<STAGES - 2>();
        __syncthreads();

        if (gc + 2 < total) fetch(gc + 2);
        cp_commit();

        const int stg = gc % 3;
        const uint32_t sA = smem_base + (uint32_t)(stg * STAGE_BYTES);
        const uint32_t sB = sA + (uint32_t)A_BYTES;

        #pragma unroll
        for (int ks = 0; ks < 4; ks++) {
            const int k0 = ks * 16;
            uint32_t af[4][4], bf[4][2];
            #pragma unroll
            for (int i = 0; i < 4; i++)
                ldsm_x4(af[i][0], af[i][1], af[i][2], af[i][3],
                        sA + (uint32_t)((a_row + i * 16) * SROW + k0 + a_col) * 2u);
            #pragma unroll
            for (int j2 = 0; j2 < 2; j2++)
                ldsm_x4(bf[j2 * 2][0], bf[j2 * 2][1], bf[j2 * 2 + 1][0], bf[j2 * 2 + 1][1],
                        sB + (uint32_t)((b_row + j2 * 16) * SROW + k0 + b_col) * 2u);
            #pragma unroll
            for (int i = 0; i < 4; i++)
                #pragma unroll
                for (int j = 0; j < 4; j++)
                    mma_f16(acc[i][j][0], acc[i][j][1], acc[i][j][2], acc[i][j][3],
                            af[i][0], af[i][1], af[i][2], af[i][3],
                            bf[j][0], bf[j][1]);
        }

        // tile boundary: store epilogue from registers (next tile's chunks already in flight)
        if ((gc & 15) == 15) {
            const int dt = tile & 7, ct = (tile >> 3) & 15, bb = tile >> 7;
            const size_t orow0 = (size_t)bb * TC + ct * 128 + wm + qg;
            const int col0 = dt * 128 + wn + t * 2;
            #pragma unroll
            for (int i = 0; i < 4; i++) {
                float* p0 = out + (orow0 + i * 16) * DD + col0;
                float* p1 = p0 + 8 * DD;
                #pragma unroll
                for (int j = 0; j < 4; j++) {
                    *reinterpret_cast<float2*>(p0 + j * 8) = make_float2(acc[i][j][0], acc[i][j][1]);
                    *reinterpret_cast<float2*>(p1 + j * 8) = make_float2(acc[i][j][2], acc[i][j][3]);
                    acc[i][j][0] = 0.f; acc[i][j][1] = 0.f;
                    acc[i][j][2] = 0.f; acc[i][j][3] = 0.f;
                }
            }
            tile += NCTA;
        }
    }
}

// ---------------- launcher ----------------
extern "C" void kernel_launch(void* const* d_in, const int* in_sizes, int n_in,
                              void* d_out, int out_size) {
    const float* sim  = (const float*)d_in[0];   // [8, 2048, 1024] fp32
    const float* qenc = (const float*)d_in[1];   // [8, 1024, 1024] fp32
    float* out = (float*)d_out;                  // [8, 2048, 1024] fp32

    cudaFuncSetAttribute(gemm_f16_kernel, cudaFuncAttributeMaxDynamicSharedMemorySize, SMEM_BYTES);

    pre_kernel<<<N_SOFTMAX_BLOCKS + N_TRANSPOSE_BLOCKS, 256>>>(sim, qenc);
    gemm_f16_kernel<<<NCTA, 256, SMEM_BYTES>>>(out);
}